// round 7
// baseline (speedup 1.0000x reference)
#include <cuda_runtime.h>
#include <cuda_fp16.h>
#include <math_constants.h>
#include <cstdint>

#define BB 1024
#define LL 256
#define DD 64
#define TDIM 100
#define NTHR 64
#define NINT 65
#define NT 1024          // weight-table intervals (table has NT+1 entries)

// Scratch in __device__ globals (no allocations allowed).
__device__ float g_T[NTHR];                            // sorted thresholds (INF pad, >0)
// Interleaved tables, row m = 16 uint4 {U01,U23,V01,V23} (half2 words):
//   P: V'_m = V_m + V0 + 2*b2   (always-loaded operand)
//   S: V'_m = V_m - V0          (predicated operand; row contribution 0 when x==0)
__device__ __align__(16) uint32_t g_TP[NINT * DD];
__device__ __align__(16) uint32_t g_TS[NINT * DD];
__device__ float g_W[NT + 1];                          // weight(t) table, t in [0,2]

// ---------------------------------------------------------------------------
// Setup kernel (single launch):
//   blocks 0..64 : sort thresholds (block 0 publishes g_T), build P/S rows
//   blocks 65..69: tabulate weight(t) = sigmoid(sum cos(t*w+b)*wts + bts)
// ---------------------------------------------------------------------------
__global__ void setup_kernel(const float* __restrict__ w1,
                             const float* __restrict__ b1,
                             const float* __restrict__ w2,
                             const float* __restrict__ b2,
                             const float* __restrict__ w_time,
                             const float* __restrict__ b_time,
                             const float* __restrict__ w_ts,
                             const float* __restrict__ b_ts) {
    const int blk = blockIdx.x;
    const int tid = threadIdx.x;
    if (blk < NINT) {
        __shared__ float sw1[NTHR], sb1[NTHR], sTin[NTHR], sTs[NTHR];
        __shared__ float spU[4 * DD], spV[4 * DD], spV0[4 * DD];
        __shared__ float sU[DD], sV[DD], sV0[DD], sb2[DD];

        if (tid < NTHR) {
            float w = w1[tid], b = b1[tid];
            sw1[tid] = w; sb1[tid] = b;
            bool crossing = (w > 0.0f && b < 0.0f) || (w < 0.0f && b > 0.0f);
            sTin[tid] = crossing ? (-b / w) : CUDART_INF_F;
        }
        if (tid < DD) sb2[tid] = b2[tid];
        __syncthreads();
        if (tid < NTHR) {
            float t = sTin[tid];
            int rank = 0;
            #pragma unroll
            for (int j = 0; j < NTHR; ++j) {
                float tj = sTin[j];
                rank += (tj < t) || (tj == t && j < tid);
            }
            sTs[rank] = t;
        }
        __syncthreads();
        if (blk == 0 && tid < NTHR) g_T[tid] = sTs[tid];

        const int m = blk;
        float lo = (m == 0)        ? 0.0f         : sTs[m - 1];
        float hi = (m == NINT - 1) ? CUDART_INF_F : sTs[m];
        float mid;
        if (!isfinite(lo))      mid = 1.0f;
        else if (!isfinite(hi)) mid = lo * 2.0f + 1.0f;
        else                    mid = 0.5f * (lo + hi);

        const int j = tid & 63;
        const int q = tid >> 6;
        float U = 0.0f, V = 0.0f, V0 = 0.0f;
        #pragma unroll 4
        for (int k2 = q * 16; k2 < q * 16 + 16; ++k2) {
            float w = sw1[k2], bb = sb1[k2];
            float w2v = w2[k2 * DD + j];
            if (fmaf(mid, w, bb) > 0.0f) {
                U = fmaf(w, w2v, U);
                V = fmaf(bb, w2v, V);
            }
            if (bb > 0.0f) V0 = fmaf(bb, w2v, V0);
        }
        spU[q * DD + j] = U; spV[q * DD + j] = V; spV0[q * DD + j] = V0;
        __syncthreads();
        if (tid < DD) {
            sU[tid]  = spU[tid]  + spU[DD + tid]  + spU[2 * DD + tid]  + spU[3 * DD + tid];
            sV[tid]  = spV[tid]  + spV[DD + tid]  + spV[2 * DD + tid]  + spV[3 * DD + tid];
            sV0[tid] = spV0[tid] + spV0[DD + tid] + spV0[2 * DD + tid] + spV0[3 * DD + tid];
        }
        __syncthreads();
        if (tid < 16) {
            const int l = tid;
            const int j0 = 4 * l;
            float u0 = sU[j0], u1 = sU[j0 + 1], u2 = sU[j0 + 2], u3 = sU[j0 + 3];
            __half2 U01 = __floats2half2_rn(u0, u1);
            __half2 U23 = __floats2half2_rn(u2, u3);
            float vp0 = sV[j0]     + sV0[j0]     + 2.0f * sb2[j0];
            float vp1 = sV[j0 + 1] + sV0[j0 + 1] + 2.0f * sb2[j0 + 1];
            float vp2 = sV[j0 + 2] + sV0[j0 + 2] + 2.0f * sb2[j0 + 2];
            float vp3 = sV[j0 + 3] + sV0[j0 + 3] + 2.0f * sb2[j0 + 3];
            float vs0 = sV[j0]     - sV0[j0];
            float vs1 = sV[j0 + 1] - sV0[j0 + 1];
            float vs2 = sV[j0 + 2] - sV0[j0 + 2];
            float vs3 = sV[j0 + 3] - sV0[j0 + 3];
            __half2 VP01 = __floats2half2_rn(vp0, vp1);
            __half2 VP23 = __floats2half2_rn(vp2, vp3);
            __half2 VS01 = __floats2half2_rn(vs0, vs1);
            __half2 VS23 = __floats2half2_rn(vs2, vs3);
            const int base = m * DD + l * 4;
            g_TP[base + 0] = *(const uint32_t*)&U01;
            g_TP[base + 1] = *(const uint32_t*)&U23;
            g_TP[base + 2] = *(const uint32_t*)&VP01;
            g_TP[base + 3] = *(const uint32_t*)&VP23;
            g_TS[base + 0] = *(const uint32_t*)&U01;
            g_TS[base + 1] = *(const uint32_t*)&U23;
            g_TS[base + 2] = *(const uint32_t*)&VS01;
            g_TS[base + 3] = *(const uint32_t*)&VS23;
        }
    } else {
        __shared__ float swt[TDIM], sbt[TDIM], sws[TDIM];
        if (tid < TDIM) {
            swt[tid] = w_time[tid];
            sbt[tid] = b_time[tid];
            sws[tid] = w_ts[tid];
        }
        __syncthreads();
        int g = (blk - NINT) * 256 + tid;
        if (g <= NT) {
            float t = (float)g * (2.0f / (float)NT);
            float acc = b_ts[0];
            #pragma unroll 4
            for (int k = 0; k < TDIM; ++k)
                acc = fmaf(__cosf(fmaf(t, swt[k], sbt[k])), sws[k], acc);
            g_W[g] = 1.0f / (1.0f + __expf(-acc));
        }
    }
}

// ---------------------------------------------------------------------------
// Main kernel helpers
// ---------------------------------------------------------------------------
__device__ __forceinline__ unsigned hash_id(int id) {
    return ((unsigned)id * 2654435761u) >> 23;
}

__device__ __forceinline__ void hash_insert(int* keys, int* cnts, int base, int id) {
    if (id == 0) return;
    unsigned slot = hash_id(id) & 511u;
    while (true) {
        int prev = atomicCAS(&keys[base + slot], 0, id);
        if (prev == 0 || prev == id) { atomicAdd(&cnts[base + slot], 1); break; }
        slot = (slot + 1) & 511u;
    }
}

__device__ __forceinline__ int hash_lookup(const int* keys, const int* cnts,
                                           int base, int id) {
    if (id == 0) return 0;
    unsigned slot = hash_id(id) & 511u;
    while (true) {
        int k = keys[base + slot];
        if (k == id) return cnts[base + slot];
        if (k == 0) return 0;
        slot = (slot + 1) & 511u;
    }
}

__device__ __forceinline__ float weight_lookup(float t) {
    float u = t * ((float)NT * 0.5f);
    u = fminf(fmaxf(u, 0.0f), (float)NT - 0.001f);
    int i0 = (int)u;
    float f = u - (float)i0;
    float a  = __ldg(&g_W[i0]);
    float bb = __ldg(&g_W[i0 + 1]);
    return fmaf(f, bb - a, a);
}

// Predicated shared v4 load, zero fallback. cond!=0 => load; else {0,0,0,0}.
// No BSSY; predicated-off => no wavefronts.
__device__ __forceinline__ uint4 lds128_pred0(uint32_t saddr, uint32_t cond) {
    uint4 r = make_uint4(0u, 0u, 0u, 0u);
    asm volatile(
        "{\n\t"
        ".reg .pred p;\n\t"
        "setp.ne.u32 p, %4, 0;\n\t"
        "@p ld.shared.v4.u32 {%0, %1, %2, %3}, [%5];\n\t"
        "}"
        : "+r"(r.x), "+r"(r.y), "+r"(r.z), "+r"(r.w)
        : "r"(cond), "r"(saddr));
    return r;
}

__device__ __forceinline__ __half2 h2(uint32_t u) { return *(const __half2*)&u; }

// ---------------------------------------------------------------------------
// Main fused kernel. One block per batch row.
// Phase A (thread-per-position): hash counts, time weights, x (fp32), m.
// Phase B (warp-cooperative): 2 positions/iter, 4 j per lane; HFMA2 math on
//   half2 {U,V'} planes; S-rows predicated with zero fallback (exact).
// ---------------------------------------------------------------------------
__global__ __launch_bounds__(LL, 6) void tni_main_kernel(
    const int*   __restrict__ src_ids,
    const int*   __restrict__ dst_ids,
    const float* __restrict__ src_times,
    const float* __restrict__ dst_times,
    const float* __restrict__ node_times,
    float*       __restrict__ out)
{
    __shared__ __align__(16) uint32_t sTab[NINT * DD * 2];  // 33,280 B; hash overlay in Phase A
    __shared__ __align__(16) uint4 sxp[LL];                 // {h2(xss,xsd), h2(xds,xdd), mm, 0}
    __shared__ float sTm[NTHR];

    const int b = blockIdx.x;
    const int i = threadIdx.x;

    // --- preamble: hash init (overlaying sTab), thresholds, ids ---
    int* keys = (int*)sTab;
    int* cnts = keys + 1024;
    #pragma unroll
    for (int t = 0; t < 8; ++t) keys[i + t * LL] = 0;
    if (i < NTHR) sTm[i] = g_T[i];

    const int sid = src_ids[b * LL + i];
    const int did = dst_ids[b * LL + i];
    __syncthreads();

    hash_insert(keys, cnts, 0,   sid);
    hash_insert(keys, cnts, 512, did);
    __syncthreads();

    const int css = hash_lookup(keys, cnts, 0,   sid);
    const int csd = hash_lookup(keys, cnts, 512, sid);
    const int cds = hash_lookup(keys, cnts, 0,   did);
    const int cdd = hash_lookup(keys, cnts, 512, did);

    const float nt = node_times[b];
    const float ws = weight_lookup(nt - src_times[b * LL + i]);
    const float wd = weight_lookup(nt - dst_times[b * LL + i]);

    const float x_ss = (float)css * ws;
    const float x_sd = (float)csd * ws;
    const float x_ds = (float)cds * wd;
    const float x_dd = (float)cdd * wd;

    // interval index m = #{T < x}; all T > 0 so x==0 -> m=0
    int m_ss = 0, m_sd = 0, m_ds = 0, m_dd = 0;
    #pragma unroll
    for (int s = 32; s >= 1; s >>= 1) {
        if (sTm[m_ss + s - 1] < x_ss) m_ss += s;
        if (sTm[m_sd + s - 1] < x_sd) m_sd += s;
        if (sTm[m_ds + s - 1] < x_ds) m_ds += s;
        if (sTm[m_dd + s - 1] < x_dd) m_dd += s;
    }
    if (sTm[m_ss] < x_ss) ++m_ss;
    if (sTm[m_sd] < x_sd) ++m_sd;
    if (sTm[m_ds] < x_ds) ++m_ds;
    if (sTm[m_dd] < x_dd) ++m_dd;

    __syncthreads();   // all hash reads done -> sTab reusable

    // --- publish packed per-position data; load P/S tables over hash region ---
    {
        __half2 hs = __floats2half2_rn(x_ss, x_sd);
        __half2 hd = __floats2half2_rn(x_ds, x_dd);
        uint32_t mm = (uint32_t)m_ss | ((uint32_t)m_sd << 8) |
                      ((uint32_t)m_ds << 16) | ((uint32_t)m_dd << 24);
        sxp[i] = make_uint4(*(const uint32_t*)&hs, *(const uint32_t*)&hd, mm, 0u);
    }
    {
        const uint4* gp4 = (const uint4*)g_TP;   // 1040 uint4 each
        const uint4* gs4 = (const uint4*)g_TS;
        uint4* st4 = (uint4*)sTab;
        #pragma unroll
        for (int t = 0; t < 5; ++t) {
            int idx = i + t * LL;
            if (idx < (NINT * DD) / 4) {
                st4[idx]                    = gp4[idx];
                st4[(NINT * DD) / 4 + idx]  = gs4[idx];
            }
        }
    }
    __syncthreads();

    // --- Phase B: warp-cooperative epilogue, 2 positions per iteration ---
    const int wid  = i >> 5;
    const int lane = i & 31;
    const int lsub = lane & 15;     // j-group: j = 4*lsub .. 4*lsub+3
    const int hsel = lane >> 4;     // which of the 2 positions

    const uint4* t4 = (const uint4*)sTab;                 // row m: 16 uint4
    const uint32_t tabs = (uint32_t)__cvta_generic_to_shared(sTab);
    const uint32_t baseS = tabs + (uint32_t)(NINT * 256) + (uint32_t)lsub * 16u;

    const size_t dst_off = (size_t)BB * LL * DD;
    const size_t brow = (size_t)b * LL;

    #pragma unroll 2
    for (int p0 = 0; p0 < 16; ++p0) {
        const int p = (wid << 5) + (p0 << 1) + hsel;
        const uint4 pk = sxp[p];           // broadcast per half-warp
        const uint32_t mm = pk.z;
        const uint32_t mss = mm & 255u;
        const uint32_t msd = (mm >> 8) & 255u;
        const uint32_t mds = (mm >> 16) & 255u;
        const uint32_t mdd = mm >> 24;

        const uint4 Ap = t4[mss * 16 + lsub];
        const uint4 Dp = t4[mdd * 16 + lsub];
        const uint4 Bs = lds128_pred0(baseS + msd * 256u, pk.x & 0xFFFF0000u);
        const uint4 Cs = lds128_pred0(baseS + mds * 256u, pk.y & 0x0000FFFFu);

        const __half2 hs = h2(pk.x);       // (x_ss, x_sd)
        const __half2 hd = h2(pk.y);       // (x_ds, x_dd)
        const __half2 xss2 = __low2half2(hs),  xsd2 = __high2half2(hs);
        const __half2 xds2 = __low2half2(hd),  xdd2 = __high2half2(hd);

        const __half2 rs01 = __hadd2(__hfma2(xss2, h2(Ap.x), h2(Ap.z)),
                                     __hfma2(xsd2, h2(Bs.x), h2(Bs.z)));
        const __half2 rs23 = __hadd2(__hfma2(xss2, h2(Ap.y), h2(Ap.w)),
                                     __hfma2(xsd2, h2(Bs.y), h2(Bs.w)));
        const __half2 rd01 = __hadd2(__hfma2(xdd2, h2(Dp.x), h2(Dp.z)),
                                     __hfma2(xds2, h2(Cs.x), h2(Cs.z)));
        const __half2 rd23 = __hadd2(__hfma2(xdd2, h2(Dp.y), h2(Dp.w)),
                                     __hfma2(xds2, h2(Cs.y), h2(Cs.w)));

        const float2 s0 = __half22float2(rs01);
        const float2 s1 = __half22float2(rs23);
        const float2 d0 = __half22float2(rd01);
        const float2 d1 = __half22float2(rd23);

        const size_t rowbase = (brow + p) * DD + 4 * lsub;
        *(float4*)(out + rowbase)           = make_float4(s0.x, s0.y, s1.x, s1.y);
        *(float4*)(out + dst_off + rowbase) = make_float4(d0.x, d0.y, d1.x, d1.y);
    }
}

// ---------------------------------------------------------------------------
// Inputs: 0 src_ids, 1 dst_ids, 2 src_times, 3 dst_times, 4 node_times,
// 5 num_nodes (unused), 6 w_time, 7 b_time, 8 w_ts, 9 b_ts, 10 w1, 11 b1,
// 12 w2, 13 b2.  Output: [src_feats (B,L,D); dst_feats (B,L,D)].
// ---------------------------------------------------------------------------
extern "C" void kernel_launch(void* const* d_in, const int* in_sizes, int n_in,
                              void* d_out, int out_size) {
    const int*   src_ids    = (const int*)  d_in[0];
    const int*   dst_ids    = (const int*)  d_in[1];
    const float* src_times  = (const float*)d_in[2];
    const float* dst_times  = (const float*)d_in[3];
    const float* node_times = (const float*)d_in[4];
    const float* w_time     = (const float*)d_in[6];
    const float* b_time     = (const float*)d_in[7];
    const float* w_ts       = (const float*)d_in[8];
    const float* b_ts       = (const float*)d_in[9];
    const float* w1         = (const float*)d_in[10];
    const float* b1         = (const float*)d_in[11];
    const float* w2         = (const float*)d_in[12];
    const float* b2         = (const float*)d_in[13];
    float*       out        = (float*)d_out;

    const int wt_blocks = (NT + 1 + 255) / 256;   // 5
    setup_kernel<<<NINT + wt_blocks, 256>>>(w1, b1, w2, b2,
                                            w_time, b_time, w_ts, b_ts);
    tni_main_kernel<<<BB, LL>>>(src_ids, dst_ids, src_times, dst_times,
                                node_times, out);
}

// round 9
// speedup vs baseline: 1.1165x; 1.1165x over previous
#include <cuda_runtime.h>
#include <cuda_fp16.h>
#include <math_constants.h>
#include <cstdint>

#define BB 1024
#define LL 256
#define DD 64
#define TDIM 100
#define NTHR 64
#define NINT 65
#define NT 1024          // weight-table intervals (table has NT+1 entries)

// Scratch in __device__ globals (no allocations allowed).
__device__ float g_T[NTHR];                    // sorted thresholds (INF pad, >0)
// Row m = 16 uint4 per plane, each {U01,U23,V01,V23} (half2 words):
//   P: V'_m = V_m + V0 + 2*b2   (always-loaded operand)
//   S: V'_m = V_m - V0          (predicated; row contribution exactly 0 when x==0)
__device__ __align__(16) uint4 g_TP4[NINT * 16];
__device__ __align__(16) uint4 g_TS4[NINT * 16];
__device__ float g_W[NT + 1];                  // weight(t) table, t in [0,2]

// ---------------------------------------------------------------------------
// Setup kernel (single launch):
//   blocks 0..64 : sort thresholds (block 0 publishes g_T), build P/S rows
//   blocks 65..69: tabulate weight(t) = sigmoid(sum cos(t*w+b)*wts + bts)
// ---------------------------------------------------------------------------
__global__ void setup_kernel(const float* __restrict__ w1,
                             const float* __restrict__ b1,
                             const float* __restrict__ w2,
                             const float* __restrict__ b2,
                             const float* __restrict__ w_time,
                             const float* __restrict__ b_time,
                             const float* __restrict__ w_ts,
                             const float* __restrict__ b_ts) {
    const int blk = blockIdx.x;
    const int tid = threadIdx.x;
    if (blk < NINT) {
        __shared__ float sw1[NTHR], sb1[NTHR], sTin[NTHR], sTs[NTHR];
        __shared__ float spU[4 * DD], spV[4 * DD], spV0[4 * DD];
        __shared__ float sU[DD], sV[DD], sV0[DD], sb2[DD];

        if (tid < NTHR) {
            float w = w1[tid], b = b1[tid];
            sw1[tid] = w; sb1[tid] = b;
            bool crossing = (w > 0.0f && b < 0.0f) || (w < 0.0f && b > 0.0f);
            sTin[tid] = crossing ? (-b / w) : CUDART_INF_F;
        }
        if (tid < DD) sb2[tid] = b2[tid];
        __syncthreads();
        if (tid < NTHR) {
            float t = sTin[tid];
            int rank = 0;
            #pragma unroll
            for (int j = 0; j < NTHR; ++j) {
                float tj = sTin[j];
                rank += (tj < t) || (tj == t && j < tid);
            }
            sTs[rank] = t;
        }
        __syncthreads();
        if (blk == 0 && tid < NTHR) g_T[tid] = sTs[tid];

        const int m = blk;
        float lo = (m == 0)        ? 0.0f         : sTs[m - 1];
        float hi = (m == NINT - 1) ? CUDART_INF_F : sTs[m];
        float mid;
        if (!isfinite(lo))      mid = 1.0f;
        else if (!isfinite(hi)) mid = lo * 2.0f + 1.0f;
        else                    mid = 0.5f * (lo + hi);

        const int j = tid & 63;
        const int q = tid >> 6;
        float U = 0.0f, V = 0.0f, V0 = 0.0f;
        #pragma unroll 4
        for (int k2 = q * 16; k2 < q * 16 + 16; ++k2) {
            float w = sw1[k2], bb = sb1[k2];
            float w2v = w2[k2 * DD + j];
            if (fmaf(mid, w, bb) > 0.0f) {
                U = fmaf(w, w2v, U);
                V = fmaf(bb, w2v, V);
            }
            if (bb > 0.0f) V0 = fmaf(bb, w2v, V0);
        }
        spU[q * DD + j] = U; spV[q * DD + j] = V; spV0[q * DD + j] = V0;
        __syncthreads();
        if (tid < DD) {
            sU[tid]  = spU[tid]  + spU[DD + tid]  + spU[2 * DD + tid]  + spU[3 * DD + tid];
            sV[tid]  = spV[tid]  + spV[DD + tid]  + spV[2 * DD + tid]  + spV[3 * DD + tid];
            sV0[tid] = spV0[tid] + spV0[DD + tid] + spV0[2 * DD + tid] + spV0[3 * DD + tid];
        }
        __syncthreads();
        if (tid < 16) {
            const int l = tid;
            const int j0 = 4 * l;
            __half2 U01 = __floats2half2_rn(sU[j0],     sU[j0 + 1]);
            __half2 U23 = __floats2half2_rn(sU[j0 + 2], sU[j0 + 3]);
            __half2 VP01 = __floats2half2_rn(sV[j0]     + sV0[j0]     + 2.0f * sb2[j0],
                                             sV[j0 + 1] + sV0[j0 + 1] + 2.0f * sb2[j0 + 1]);
            __half2 VP23 = __floats2half2_rn(sV[j0 + 2] + sV0[j0 + 2] + 2.0f * sb2[j0 + 2],
                                             sV[j0 + 3] + sV0[j0 + 3] + 2.0f * sb2[j0 + 3]);
            __half2 VS01 = __floats2half2_rn(sV[j0]     - sV0[j0],
                                             sV[j0 + 1] - sV0[j0 + 1]);
            __half2 VS23 = __floats2half2_rn(sV[j0 + 2] - sV0[j0 + 2],
                                             sV[j0 + 3] - sV0[j0 + 3]);
            g_TP4[m * 16 + l] = make_uint4(*(const uint32_t*)&U01, *(const uint32_t*)&U23,
                                           *(const uint32_t*)&VP01, *(const uint32_t*)&VP23);
            g_TS4[m * 16 + l] = make_uint4(*(const uint32_t*)&U01, *(const uint32_t*)&U23,
                                           *(const uint32_t*)&VS01, *(const uint32_t*)&VS23);
        }
    } else {
        __shared__ float swt[TDIM], sbt[TDIM], sws[TDIM];
        if (tid < TDIM) {
            swt[tid] = w_time[tid];
            sbt[tid] = b_time[tid];
            sws[tid] = w_ts[tid];
        }
        __syncthreads();
        int g = (blk - NINT) * 256 + tid;
        if (g <= NT) {
            float t = (float)g * (2.0f / (float)NT);
            float acc = b_ts[0];
            #pragma unroll 4
            for (int k = 0; k < TDIM; ++k)
                acc = fmaf(__cosf(fmaf(t, swt[k], sbt[k])), sws[k], acc);
            g_W[g] = 1.0f / (1.0f + __expf(-acc));
        }
    }
}

// ---------------------------------------------------------------------------
// Main kernel helpers
// ---------------------------------------------------------------------------
__device__ __forceinline__ unsigned hash_id(int id) {
    return ((unsigned)id * 2654435761u) >> 23;
}

__device__ __forceinline__ void hash_insert(int* keys, int* cnts, int base, int id) {
    if (id == 0) return;
    unsigned slot = hash_id(id) & 511u;
    while (true) {
        int prev = atomicCAS(&keys[base + slot], 0, id);
        if (prev == 0 || prev == id) { atomicAdd(&cnts[base + slot], 1); break; }
        slot = (slot + 1) & 511u;
    }
}

__device__ __forceinline__ int hash_lookup(const int* keys, const int* cnts,
                                           int base, int id) {
    if (id == 0) return 0;
    unsigned slot = hash_id(id) & 511u;
    while (true) {
        int k = keys[base + slot];
        if (k == id) return cnts[base + slot];
        if (k == 0) return 0;
        slot = (slot + 1) & 511u;
    }
}

__device__ __forceinline__ float weight_lookup(float t) {
    float u = t * ((float)NT * 0.5f);
    u = fminf(fmaxf(u, 0.0f), (float)NT - 0.001f);
    int i0 = (int)u;
    float f = u - (float)i0;
    float a  = __ldg(&g_W[i0]);
    float bb = __ldg(&g_W[i0 + 1]);
    return fmaf(f, bb - a, a);
}

// Predicated global v4 load, zero fallback. cond!=0 => load; else {0,0,0,0}.
// No BSSY; predicated-off => no L1 wavefronts.
__device__ __forceinline__ uint4 ldg128_pred0(const uint4* addr, uint32_t cond) {
    uint4 r = make_uint4(0u, 0u, 0u, 0u);
    asm volatile(
        "{\n\t"
        ".reg .pred p;\n\t"
        "setp.ne.u32 p, %4, 0;\n\t"
        "@p ld.global.nc.v4.u32 {%0, %1, %2, %3}, [%5];\n\t"
        "}"
        : "+r"(r.x), "+r"(r.y), "+r"(r.z), "+r"(r.w)
        : "r"(cond), "l"(addr));
    return r;
}

__device__ __forceinline__ __half2 h2(uint32_t u) { return *(const __half2*)&u; }

// ---------------------------------------------------------------------------
// Main fused kernel. One block per batch row, 2 barriers total.
// Phase A (thread-per-position): hash counts, time weights, x, interval m.
// Phase B (per-warp, no barrier): 2 positions/iter via shfl broadcast of the
//   warp's own lanes; HFMA2 on half2 {U,V'} planes read straight from global
//   (L1-resident tables); S-rows predicated with zero fallback (exact).
// ---------------------------------------------------------------------------
__global__ __launch_bounds__(LL, 8) void tni_main_kernel(
    const int*   __restrict__ src_ids,
    const int*   __restrict__ dst_ids,
    const float* __restrict__ src_times,
    const float* __restrict__ dst_times,
    const float* __restrict__ node_times,
    float*       __restrict__ out)
{
    __shared__ __align__(16) int sHash[2048];   // keys [0..1023], counts [1024..2047]
    __shared__ float sTm[NTHR];

    const int b = blockIdx.x;
    const int i = threadIdx.x;

    // --- preamble: hash zero, thresholds, ids ---
    #pragma unroll
    for (int t = 0; t < 2; ++t)
        ((int4*)sHash)[i + t * LL] = make_int4(0, 0, 0, 0);
    if (i < NTHR) sTm[i] = g_T[i];

    const int sid = src_ids[b * LL + i];
    const int did = dst_ids[b * LL + i];
    __syncthreads();

    int* keys = sHash;
    int* cnts = sHash + 1024;
    hash_insert(keys, cnts, 0,   sid);
    hash_insert(keys, cnts, 512, did);
    __syncthreads();

    const int css = hash_lookup(keys, cnts, 0,   sid);
    const int csd = hash_lookup(keys, cnts, 512, sid);
    const int cds = hash_lookup(keys, cnts, 0,   did);
    const int cdd = hash_lookup(keys, cnts, 512, did);

    const float nt = node_times[b];
    const float ws = weight_lookup(nt - src_times[b * LL + i]);
    const float wd = weight_lookup(nt - dst_times[b * LL + i]);

    const float x_ss = (float)css * ws;
    const float x_sd = (float)csd * ws;
    const float x_ds = (float)cds * wd;
    const float x_dd = (float)cdd * wd;

    // interval index m = #{T < x}; all T > 0 so x==0 -> m=0
    int m_ss = 0, m_sd = 0, m_ds = 0, m_dd = 0;
    #pragma unroll
    for (int s = 32; s >= 1; s >>= 1) {
        if (sTm[m_ss + s - 1] < x_ss) m_ss += s;
        if (sTm[m_sd + s - 1] < x_sd) m_sd += s;
        if (sTm[m_ds + s - 1] < x_ds) m_ds += s;
        if (sTm[m_dd + s - 1] < x_dd) m_dd += s;
    }
    if (sTm[m_ss] < x_ss) ++m_ss;
    if (sTm[m_sd] < x_sd) ++m_sd;
    if (sTm[m_ds] < x_ds) ++m_ds;
    if (sTm[m_dd] < x_dd) ++m_dd;

    // pack per-position data in registers (warp-local exchange via shfl)
    __half2 hxs = __floats2half2_rn(x_ss, x_sd);
    __half2 hxd = __floats2half2_rn(x_ds, x_dd);
    const uint32_t pk0 = *(const uint32_t*)&hxs;
    const uint32_t pk1 = *(const uint32_t*)&hxd;
    const uint32_t pkm = (uint32_t)m_ss | ((uint32_t)m_sd << 8) |
                         ((uint32_t)m_ds << 16) | ((uint32_t)m_dd << 24);

    // --- Phase B: per-warp epilogue, 2 positions per iteration, no barrier ---
    const int wid  = i >> 5;
    const int lane = i & 31;
    const int lsub = lane & 15;     // j-group: j = 4*lsub .. 4*lsub+3
    const int hsel = lane >> 4;     // which of the 2 positions

    const uint4* __restrict__ TP = g_TP4;
    const uint4* __restrict__ TS = g_TS4;
    const size_t dst_off = (size_t)BB * LL * DD;
    const size_t brow = (size_t)b * LL;

    #pragma unroll 2
    for (int p0 = 0; p0 < 16; ++p0) {
        const int src = (p0 << 1) + hsel;
        const uint32_t qx = __shfl_sync(0xFFFFFFFFu, pk0, src);
        const uint32_t qy = __shfl_sync(0xFFFFFFFFu, pk1, src);
        const uint32_t mm = __shfl_sync(0xFFFFFFFFu, pkm, src);

        const uint32_t mss = mm & 255u;
        const uint32_t msd = (mm >> 8) & 255u;
        const uint32_t mds = (mm >> 16) & 255u;
        const uint32_t mdd = mm >> 24;

        const uint4 Ap = __ldg(&TP[mss * 16 + lsub]);
        const uint4 Dp = __ldg(&TP[mdd * 16 + lsub]);
        const uint4 Bs = ldg128_pred0(&TS[msd * 16 + lsub], qx & 0xFFFF0000u);
        const uint4 Cs = ldg128_pred0(&TS[mds * 16 + lsub], qy & 0x0000FFFFu);

        const __half2 hs = h2(qx);         // (x_ss, x_sd)
        const __half2 hd = h2(qy);         // (x_ds, x_dd)
        const __half2 xss2 = __low2half2(hs),  xsd2 = __high2half2(hs);
        const __half2 xds2 = __low2half2(hd),  xdd2 = __high2half2(hd);

        const __half2 rs01 = __hadd2(__hfma2(xss2, h2(Ap.x), h2(Ap.z)),
                                     __hfma2(xsd2, h2(Bs.x), h2(Bs.z)));
        const __half2 rs23 = __hadd2(__hfma2(xss2, h2(Ap.y), h2(Ap.w)),
                                     __hfma2(xsd2, h2(Bs.y), h2(Bs.w)));
        const __half2 rd01 = __hadd2(__hfma2(xdd2, h2(Dp.x), h2(Dp.z)),
                                     __hfma2(xds2, h2(Cs.x), h2(Cs.z)));
        const __half2 rd23 = __hadd2(__hfma2(xdd2, h2(Dp.y), h2(Dp.w)),
                                     __hfma2(xds2, h2(Cs.y), h2(Cs.w)));

        const float2 s0 = __half22float2(rs01);
        const float2 s1 = __half22float2(rs23);
        const float2 d0 = __half22float2(rd01);
        const float2 d1 = __half22float2(rd23);

        const int p = (wid << 5) + (p0 << 1) + hsel;
        const size_t rowbase = (brow + p) * DD + 4 * lsub;
        *(float4*)(out + rowbase)           = make_float4(s0.x, s0.y, s1.x, s1.y);
        *(float4*)(out + dst_off + rowbase) = make_float4(d0.x, d0.y, d1.x, d1.y);
    }
}

// ---------------------------------------------------------------------------
// Inputs: 0 src_ids, 1 dst_ids, 2 src_times, 3 dst_times, 4 node_times,
// 5 num_nodes (unused), 6 w_time, 7 b_time, 8 w_ts, 9 b_ts, 10 w1, 11 b1,
// 12 w2, 13 b2.  Output: [src_feats (B,L,D); dst_feats (B,L,D)].
// ---------------------------------------------------------------------------
extern "C" void kernel_launch(void* const* d_in, const int* in_sizes, int n_in,
                              void* d_out, int out_size) {
    const int*   src_ids    = (const int*)  d_in[0];
    const int*   dst_ids    = (const int*)  d_in[1];
    const float* src_times  = (const float*)d_in[2];
    const float* dst_times  = (const float*)d_in[3];
    const float* node_times = (const float*)d_in[4];
    const float* w_time     = (const float*)d_in[6];
    const float* b_time     = (const float*)d_in[7];
    const float* w_ts       = (const float*)d_in[8];
    const float* b_ts       = (const float*)d_in[9];
    const float* w1         = (const float*)d_in[10];
    const float* b1         = (const float*)d_in[11];
    const float* w2         = (const float*)d_in[12];
    const float* b2         = (const float*)d_in[13];
    float*       out        = (float*)d_out;

    const int wt_blocks = (NT + 1 + 255) / 256;   // 5
    setup_kernel<<<NINT + wt_blocks, 256>>>(w1, b1, w2, b2,
                                            w_time, b_time, w_ts, b_ts);
    tni_main_kernel<<<BB, LL>>>(src_ids, dst_ids, src_times, dst_times,
                                node_times, out);
}